// round 11
// baseline (speedup 1.0000x reference)
#include <cuda_runtime.h>
#include <cstdint>

// ActionSmoothingLoss: segmented log-softmax KL
// NVEC = (3,3,4,25,25,8), A = 68, W = 524288
// Hybrid dual-path streaming: TMA bulk ring (threads 0-127) + warp-autonomous
// cp.async pipelines (threads 128-255), disjoint row halves.

#define A_DIM        68
#define NSEG         6
#define BLOCK        256
#define GRP          128
// TMA side
#define RPS          128                       // rows per TMA stage
#define STAGE_FLOATS (RPS * A_DIM)             // 8704
#define STAGE_BYTES  (STAGE_FLOATS * 4)        // 34816
#define NSLOTS       3
// LSU side
#define LWARPS       4                         // warps in LSU group
#define RPC          32                        // rows per LSU chunk
#define F4_CHUNK     (RPC * 17)                // 544
#define GRID_MAX     148

__device__ double g_part[GRID_MAX];
__device__ unsigned int g_count = 0;           // returns to 0 each call

#define SEG_OF(k) ((k) < 3 ? 0 : (k) < 6 ? 1 : (k) < 10 ? 2 : (k) < 35 ? 3 : (k) < 60 ? 4 : 5)

__device__ __forceinline__ uint32_t s2u(const void* p) {
    return (uint32_t)__cvta_generic_to_shared(p);
}
__device__ __forceinline__ void mbar_init(uint32_t a, uint32_t cnt) {
    asm volatile("mbarrier.init.shared.b64 [%0], %1;" :: "r"(a), "r"(cnt) : "memory");
}
__device__ __forceinline__ void mbar_expect_tx(uint32_t a, uint32_t bytes) {
    asm volatile("mbarrier.arrive.expect_tx.shared.b64 _, [%0], %1;" :: "r"(a), "r"(bytes) : "memory");
}
__device__ __forceinline__ void mbar_arrive(uint32_t a) {
    asm volatile("mbarrier.arrive.shared.b64 _, [%0];" :: "r"(a) : "memory");
}
__device__ __forceinline__ void mbar_wait(uint32_t a, uint32_t ph) {
    uint32_t done;
    do {
        asm volatile("{\n\t.reg .pred p;\n\t"
                     "mbarrier.try_wait.parity.acquire.cta.shared::cta.b64 p, [%1], %2, 0x989680;\n\t"
                     "selp.b32 %0, 1, 0, p;\n\t}"
                     : "=r"(done) : "r"(a), "r"(ph) : "memory");
    } while (!done);
}
__device__ __forceinline__ void bulk_g2s(uint32_t dst, const void* src,
                                         uint32_t bytes, uint32_t mbar) {
    asm volatile("cp.async.bulk.shared::cluster.global.mbarrier::complete_tx::bytes "
                 "[%0], [%1], %2, [%3];"
                 :: "r"(dst), "l"(src), "r"(bytes), "r"(mbar) : "memory");
}
__device__ __forceinline__ void cp16g(uint32_t dst, const void* src, int bytes) {
    asm volatile("cp.async.cg.shared.global [%0], [%1], 16, %2;\n"
                 :: "r"(dst), "l"(src), "r"(bytes));
}
__device__ __forceinline__ void cp16(uint32_t dst, const void* src) {
    asm volatile("cp.async.cg.shared.global [%0], [%1], 16;\n"
                 :: "r"(dst), "l"(src));
}
__device__ __forceinline__ void cp_commit() { asm volatile("cp.async.commit_group;\n"); }
__device__ __forceinline__ void cp_wait1()  { asm volatile("cp.async.wait_group 1;\n" ::: "memory"); }
__device__ __forceinline__ void cp_wait0()  { asm volatile("cp.async.wait_group 0;\n" ::: "memory"); }

extern __shared__ float dynsmem[];
// layout: [0, NSLOTS*STAGE_FLOATS)                       TMA slots   (104448 B)
//         [NSLOTS*STAGE_FLOATS, + LWARPS*2*F4_CHUNK*4)   LSU buffers ( 69632 B)
#define LSU_BASE (NSLOTS * STAGE_FLOATS)

// shared inner loop: accumulate one 68-float row from smem, return row loss
__device__ __forceinline__ float row_loss_from_smem(const float* rowf,
                                                    const float* __restrict__ xs)
{
    const float4* row = reinterpret_cast<const float4*>(rowf);
    float s[NSEG] = {0,0,0,0,0,0};
    float a[NSEG] = {0,0,0,0,0,0};
    #pragma unroll
    for (int i = 0; i < 17; i++) {
        const float4 v = row[i];
        const float vv[4] = {v.x, v.y, v.z, v.w};
        #pragma unroll
        for (int k2 = 0; k2 < 4; k2++) {
            const int idx = 4 * i + k2;
            const int jj = SEG_OF(idx);
            const float r = vv[k2];
            const float e = __expf(r);
            s[jj] += e;
            a[jj] = fmaf(e, r - xs[idx], a[jj]);
        }
    }
    const float invn[NSEG] = {1.f/3.f, 1.f/3.f, 1.f/4.f, 1.f/25.f, 1.f/25.f, 1.f/8.f};
    float rl = 0.f;
    #pragma unroll
    for (int jj = 0; jj < NSEG; jj++)
        rl += invn[jj] * (__fdividef(a[jj], s[jj]) - __logf(s[jj]));
    return rl;
}

__global__ void __launch_bounds__(BLOCK, 1) asl_kernel(
    const float* __restrict__ cur,
    const float* __restrict__ prev,
    float* __restrict__ out,
    int W, int Wt, int nstagesT, int nchunksL, int nblocks)
{
    __shared__ __align__(8) uint64_t full_bar[NSLOTS];
    __shared__ __align__(8) uint64_t empty_bar[NSLOTS];
    __shared__ float xs[A_DIM];
    __shared__ double wred[BLOCK / 32];
    __shared__ bool is_last;

    const int tid  = threadIdx.x;
    const int warp = tid >> 5;
    const int lane = tid & 31;

    // --- init barriers + current_action log-softmax ---
    if (tid < A_DIM) xs[tid] = cur[tid];
    if (tid == 0) {
        #pragma unroll
        for (int s = 0; s < NSLOTS; s++) {
            mbar_init(s2u(&full_bar[s]), 1);
            mbar_init(s2u(&empty_bar[s]), GRP);
        }
    }
    __syncthreads();
    asm volatile("fence.proxy.async.shared::cta;" ::: "memory");
    if (tid < NSEG) {
        const int off[NSEG] = {0, 3, 6, 10, 35, 60};
        const int sz[NSEG]  = {3, 3, 4, 25, 25, 8};
        const int o = off[tid], n = sz[tid];
        float s = 0.f;
        for (int i = 0; i < n; i++) s += __expf(xs[o + i]);
        const float L = __logf(s);
        for (int i = 0; i < n; i++) xs[o + i] -= L;
    }
    __syncthreads();

    double acc_d = 0.0;
    const char* gbase = reinterpret_cast<const char*>(prev);

    if (tid < GRP) {
        // ============ Group T: TMA bulk ring over rows [0, Wt) ============
        const int gt = tid;
        int myiters = 0;
        if (blockIdx.x < nstagesT)
            myiters = (nstagesT - 1 - blockIdx.x) / nblocks + 1;

        auto issue = [&](int j) {              // gt==0 only
            const int stage = blockIdx.x + j * nblocks;
            const int slot  = j % NSLOTS;
            const size_t row0 = (size_t)stage * RPS;
            int rows = Wt - (int)row0; if (rows > RPS) rows = RPS;
            const uint32_t bytes = (uint32_t)rows * (A_DIM * 4);
            const uint32_t fb = s2u(&full_bar[slot]);
            mbar_expect_tx(fb, bytes);
            bulk_g2s(s2u(dynsmem + (size_t)slot * STAGE_FLOATS),
                     gbase + row0 * (A_DIM * 4), bytes, fb);
        };

        if (gt == 0) {
            const int np = myiters < NSLOTS ? myiters : NSLOTS;
            for (int j = 0; j < np; j++) issue(j);
        }

        for (int j = 0; j < myiters; j++) {
            const int slot = j % NSLOTS;
            const uint32_t ph = (uint32_t)((j / NSLOTS) & 1);
            mbar_wait(s2u(&full_bar[slot]), ph);

            const int stage = blockIdx.x + j * nblocks;
            const int w = stage * RPS + gt;
            if (w < Wt)
                acc_d += (double)row_loss_from_smem(
                    dynsmem + (size_t)slot * STAGE_FLOATS + gt * A_DIM, xs);

            mbar_arrive(s2u(&empty_bar[slot]));
            if (gt == 0 && j + NSLOTS < myiters) {
                mbar_wait(s2u(&empty_bar[slot]), ph);
                issue(j + NSLOTS);
            }
        }
    } else {
        // ============ Group L: warp cp.async pipelines over rows [Wt, W) ============
        const int lw = warp - LWARPS;          // 0..3
        float* mybuf = dynsmem + LSU_BASE + (size_t)lw * (2 * F4_CHUNK * 4);
        float* bufp[2] = { mybuf, mybuf + F4_CHUNK * 4 };
        const uint32_t sbb[2] = { s2u(bufp[0]), s2u(bufp[1]) };

        const size_t base_f4  = (size_t)Wt * 17;       // f4 offset of LSU half
        const size_t total_f4 = ((size_t)W * A_DIM) >> 2;
        const float4* gp = reinterpret_cast<const float4*>(prev);

        const int total_warps = nblocks * LWARPS;
        const int gw = blockIdx.x * LWARPS + lw;

        auto stage_l = [&](int chunk, int b) {
            const size_t cb = base_f4 + (size_t)chunk * F4_CHUNK;
            const float4* src = gp + cb + lane;
            const uint32_t dst = sbb[b] + (uint32_t)lane * 16;
            if (cb + F4_CHUNK <= total_f4) {
                #pragma unroll
                for (int k = 0; k < 17; k++) cp16(dst + k * (32 * 16), src + k * 32);
            } else {
                #pragma unroll
                for (int k = 0; k < 17; k++) {
                    const size_t g = cb + lane + (size_t)k * 32;
                    cp16g(dst + k * (32 * 16), src + k * 32, g < total_f4 ? 16 : 0);
                }
            }
            cp_commit();
        };

        int pending = 0;
        if (gw < nchunksL) { stage_l(gw, 0); pending++; }
        if (gw + total_warps < nchunksL) { stage_l(gw + total_warps, 1); pending++; }

        int bi = 0;
        for (int c = gw; c < nchunksL; c += total_warps) {
            if (pending == 2) cp_wait1(); else cp_wait0();
            __syncwarp();

            const int w = Wt + c * RPC + lane;
            if (w < W)
                acc_d += (double)row_loss_from_smem(bufp[bi] + lane * A_DIM, xs);
            __syncwarp();

            pending--;
            const int nxt = c + 2 * total_warps;
            if (nxt < nchunksL) { stage_l(nxt, bi); pending++; }
            bi ^= 1;
        }
    }

    __syncthreads();

    // --- block reduction (double), deterministic ---
    double d = acc_d;
    #pragma unroll
    for (int st = 16; st > 0; st >>= 1)
        d += __shfl_down_sync(0xFFFFFFFFu, d, st);
    if (lane == 0) wred[warp] = d;
    __syncthreads();
    if (tid == 0) {
        double b = 0.0;
        #pragma unroll
        for (int k = 0; k < BLOCK / 32; k++) b += wred[k];
        g_part[blockIdx.x] = b;
        __threadfence();
        unsigned int t = atomicAdd(&g_count, 1u);
        is_last = (t == (unsigned int)(nblocks - 1));
    }
    __syncthreads();

    if (is_last) {
        double a2 = 0.0;
        for (int k = tid; k < nblocks; k += BLOCK) a2 += g_part[k];
        #pragma unroll
        for (int st = 16; st > 0; st >>= 1)
            a2 += __shfl_down_sync(0xFFFFFFFFu, a2, st);
        if (lane == 0) wred[warp] = a2;
        __syncthreads();
        if (tid == 0) {
            double tot = 0.0;
            #pragma unroll
            for (int k = 0; k < BLOCK / 32; k++) tot += wred[k];
            out[0] = (float)(tot / (double)W);
            g_count = 0;
        }
    }
}

extern "C" void kernel_launch(void* const* d_in, const int* in_sizes, int n_in,
                              void* d_out, int out_size)
{
    const float* cur  = (const float*)d_in[0];   // [68]
    const float* prev = (const float*)d_in[1];   // [W, 68]
    const int W = in_sizes[1] / A_DIM;

    // TMA half: rows [0, Wt), multiple of RPS; LSU half: rows [Wt, W)
    int Wt = ((W / 2 + RPS - 1) / RPS) * RPS;
    if (Wt > W) Wt = W;
    const int nstagesT = Wt / RPS;
    const int nchunksL = (W - Wt + RPC - 1) / RPC;

    int nblocks = GRID_MAX;
    if (nblocks > nstagesT && nstagesT > 0) nblocks = nstagesT;
    if (nblocks < 1) nblocks = 1;

    const int dyn = NSLOTS * STAGE_BYTES + LWARPS * 2 * F4_CHUNK * 16;  // 174080 B
    static int configured = 0;
    if (!configured) {
        cudaFuncSetAttribute(asl_kernel,
                             cudaFuncAttributeMaxDynamicSharedMemorySize, dyn);
        configured = 1;
    }

    asl_kernel<<<nblocks, BLOCK, dyn>>>(cur, prev, (float*)d_out,
                                        W, Wt, nstagesT, nchunksL, nblocks);
}